// round 5
// baseline (speedup 1.0000x reference)
#include <cuda_runtime.h>
#include <math.h>

#define NIMG 8
#define HH 36
#define WW 36
#define HWTOK 1296
#define HP 38
#define RCH 128
#define NHEAD 8
#define HEADC 16
#define LOG2E 1.44269504088896340736f

typedef unsigned long long ull;

// ---------------- scratch (device globals; zero-init at load) ----------------
__device__ float g_xtp[(size_t)NIMG*RCH*HP*HP];     // padded tanh(in-proj); borders stay 0
__device__ float g_za [(size_t)NIMG*256*HWTOK];     // [z | a]
__device__ float g_q  [(size_t)NIMG*RCH*HWTOK];
__device__ float g_k  [(size_t)NIMG*RCH*HWTOK];
__device__ float g_v  [(size_t)NIMG*RCH*HWTOK];
__device__ float g_h  [(size_t)NIMG*RCH*HWTOK];
__device__ float g_pre[3][(size_t)NIMG*RCH*HWTOK];  // gate pre-activations i,g,o
__device__ float g_pat[2][(size_t)NIMG*NHEAD*HEADC*HWTOK]; // attn partial sums per j-half
__device__ float g_plen[2][(size_t)NIMG*NHEAD*HWTOK];      // attn partial l per j-half

// transposed weights ([in][out], coalesced for GEMM smem fills)
__device__ float g_wt_in [128*128];
__device__ float g_wt_q  [128*128];
__device__ float g_wt_k  [128*128];
__device__ float g_wt_v  [128*128];
__device__ float g_wt_out[128*128];
__device__ float g_wt_i  [256*128];
__device__ float g_wt_g  [256*128];
__device__ float g_wt_o  [256*128];
__device__ float g_wt_conv[1152*128];               // [(ci*9+tap)][o], ci<128 only

// ---------------- helpers ----------------
__device__ __forceinline__ float tanh_fast(float x){
    float r; asm("tanh.approx.f32 %0, %1;" : "=f"(r) : "f"(x)); return r;
}
__device__ __forceinline__ float sigmoid_fast(float x){
    return 0.5f * tanh_fast(0.5f * x) + 0.5f;
}
__device__ __forceinline__ float ex2_fast(float x){
    float r; asm("ex2.approx.f32 %0, %1;" : "=f"(r) : "f"(x)); return r;
}
__device__ __forceinline__ ull pack2(float a, float b){
    ull r; asm("mov.b64 %0, {%1,%2};" : "=l"(r) : "f"(a), "f"(b)); return r;
}
__device__ __forceinline__ ull pack1(float a){
    ull r; asm("mov.b64 %0, {%1,%1};" : "=l"(r) : "f"(a)); return r;
}
__device__ __forceinline__ void unpack2(ull v, float& a, float& b){
    asm("mov.b64 {%0,%1}, %2;" : "=f"(a), "=f"(b) : "l"(v));
}
__device__ __forceinline__ ull mul2(ull a, ull b){
    ull d; asm("mul.rn.f32x2 %0, %1, %2;" : "=l"(d) : "l"(a), "l"(b)); return d;
}
__device__ __forceinline__ ull fma2r(ull a, ull b, ull c){
    ull d; asm("fma.rn.f32x2 %0, %1, %2, %3;" : "=l"(d) : "l"(a), "l"(b), "l"(c)); return d;
}

// ---------------- weight repack ----------------
__global__ void repack_all(const float* __restrict__ w_in, const float* __restrict__ wq,
                           const float* __restrict__ wk,   const float* __restrict__ wv,
                           const float* __restrict__ w_i,  const float* __restrict__ w_g,
                           const float* __restrict__ w_o,  const float* __restrict__ w_out,
                           const float* __restrict__ w_conv)
{
    int idx = blockIdx.x*256 + threadIdx.x;
    if (idx < 5*16384) {
        int m = idx >> 14; int r = idx & 16383; int o = r >> 7; int i = r & 127;
        float v;
        if      (m==0) v = w_in[r];
        else if (m==1) v = wq[r];
        else if (m==2) v = wk[r];
        else if (m==3) v = wv[r];
        else           v = w_out[r];
        float* d = (m==0)?g_wt_in:(m==1)?g_wt_q:(m==2)?g_wt_k:(m==3)?g_wt_v:g_wt_out;
        d[i*128+o] = v;
    } else if (idx < 5*16384 + 3*32768) {
        int r = idx - 5*16384; int m = r >> 15; int rr = r & 32767;
        int o = rr >> 8; int i = rr & 255;    // src [128][256]
        float v = (m==0) ? w_i[rr] : (m==1) ? w_g[rr] : w_o[rr];
        float* d = (m==0)?g_wt_i:(m==1)?g_wt_g:g_wt_o;
        d[i*128+o] = v;
    } else if (idx < 5*16384 + 3*32768 + 147456) {
        int r = idx - (5*16384 + 3*32768);
        int o = r / 1152; int rem = r - o*1152;         // rem = ci*9+tap, ci<128
        g_wt_conv[rem*128 + o] = w_conv[(size_t)o*2304 + rem];
    }
}

// ---------------- big GEMM core: 128 tok x 128 out, 4tok x 16out/thread ----------------
template<int KSTEPS>
__device__ __forceinline__ void gemm_core_big(const float* __restrict__ xn,
                                              const float* __restrict__ wt,
                                              int t0, ull (&acc2)[8][4],
                                              float (*xs)[16][128], float (*ws)[16][128])
{
    const int tid = threadIdx.x;
    const int tt = tid & 31;     // 32 token groups x 4
    const int og = tid >> 5;     // 8 out groups x 16
    float xr[8], wr[8];
    #pragma unroll
    for (int r=0;r<8;r++){
        int idx = tid + r*256, i = idx>>7, t = idx&127, gt = t0+t;
        xr[r] = (gt<HWTOK) ? xn[(size_t)i*HWTOK+gt] : 0.f;
        wr[r] = wt[i*128 + (idx&127)];
    }
    #pragma unroll
    for (int r=0;r<8;r++){
        int idx = tid + r*256;
        xs[0][idx>>7][idx&127] = xr[r];
        ws[0][idx>>7][idx&127] = wr[r];
    }
    __syncthreads();

    for (int s=0; s<KSTEPS; s++){
        const int b = s&1;
        if (s<KSTEPS-1){
            const int kc=(s+1)*16;
            #pragma unroll
            for (int r=0;r<8;r++){
                int idx = tid + r*256, i = idx>>7, t = idx&127, gt = t0+t;
                xr[r] = (gt<HWTOK) ? xn[(size_t)(kc+i)*HWTOK+gt] : 0.f;
                wr[r] = wt[(kc+i)*128 + (idx&127)];
            }
        }
        #pragma unroll
        for (int i=0;i<16;i++){
            float4 xv = *(const float4*)&xs[b][i][tt*4];
            ull xb[4] = {pack1(xv.x), pack1(xv.y), pack1(xv.z), pack1(xv.w)};
            ulonglong2 w0 = *(const ulonglong2*)&ws[b][i][og*16];
            ulonglong2 w1 = *(const ulonglong2*)&ws[b][i][og*16+4];
            ulonglong2 w2 = *(const ulonglong2*)&ws[b][i][og*16+8];
            ulonglong2 w3 = *(const ulonglong2*)&ws[b][i][og*16+12];
            ull wp[8] = {w0.x,w0.y,w1.x,w1.y,w2.x,w2.y,w3.x,w3.y};
            #pragma unroll
            for (int p=0;p<8;p++)
                #pragma unroll
                for (int t=0;t<4;t++)
                    acc2[p][t] = fma2r(xb[t], wp[p], acc2[p][t]);
        }
        if (s<KSTEPS-1){
            const int nb = (s&1)^1;
            #pragma unroll
            for (int r=0;r<8;r++){
                int idx = tid + r*256;
                xs[nb][idx>>7][idx&127] = xr[r];
                ws[nb][idx>>7][idx&127] = wr[r];
            }
        }
        __syncthreads();
    }
}

// ---------------- qkv: big tile; z selects matrix ----------------
__global__ __launch_bounds__(256,2) void qkv_kernel()
{
    __shared__ float xs[2][16][128];
    __shared__ float ws[2][16][128];
    const int n  = blockIdx.y;
    const int z  = blockIdx.z;
    const int t0 = blockIdx.x * 128;
    const int tt = threadIdx.x & 31;
    const int og = threadIdx.x >> 5;
    const float* wt = (z==0) ? g_wt_q : (z==1) ? g_wt_k : g_wt_v;
    float* dst      = (z==0) ? g_q    : (z==1) ? g_k    : g_v;
    ull acc2[8][4];
    #pragma unroll
    for (int p=0;p<8;p++) for (int t=0;t<4;t++) acc2[p][t] = 0ull;
    gemm_core_big<8>(g_za + (size_t)n*256*HWTOK, wt, t0, acc2, xs, ws);
    #pragma unroll
    for (int p=0;p<8;p++){
        int oc0 = og*16 + 2*p;
        #pragma unroll
        for (int t=0;t<4;t++){
            int gt = t0 + tt*4 + t;
            if (gt >= HWTOK) continue;
            float v0, v1; unpack2(acc2[p][t], v0, v1);
            dst[((size_t)n*RCH+oc0)*HWTOK+gt]   = v0;
            dst[((size_t)n*RCH+oc0+1)*HWTOK+gt] = v1;
        }
    }
}

// ---------------- gates GEMM: big tile; z in {i,g,o} ----------------
__global__ __launch_bounds__(256,2) void gates_gemm_kernel()
{
    __shared__ float xs[2][16][128];
    __shared__ float ws[2][16][128];
    const int n  = blockIdx.y;
    const int z  = blockIdx.z;
    const int t0 = blockIdx.x * 128;
    const int tt = threadIdx.x & 31;
    const int og = threadIdx.x >> 5;
    const float* wt = (z==0) ? g_wt_i : (z==1) ? g_wt_g : g_wt_o;
    float* dst = g_pre[z];
    ull acc2[8][4];
    #pragma unroll
    for (int p=0;p<8;p++) for (int t=0;t<4;t++) acc2[p][t] = 0ull;
    gemm_core_big<16>(g_za + (size_t)n*256*HWTOK, wt, t0, acc2, xs, ws);
    #pragma unroll
    for (int p=0;p<8;p++){
        int oc0 = og*16 + 2*p;
        #pragma unroll
        for (int t=0;t<4;t++){
            int gt = t0 + tt*4 + t;
            if (gt >= HWTOK) continue;
            float v0, v1; unpack2(acc2[p][t], v0, v1);
            dst[((size_t)n*RCH+oc0)*HWTOK+gt]   = v0;
            dst[((size_t)n*RCH+oc0+1)*HWTOK+gt] = v1;
        }
    }
}

// ---------------- small GEMM core (64 tok) for in/out proj ----------------
template<int KSTEPS>
__device__ __forceinline__ void gemm_core(const float* __restrict__ xn,
                                          const float* __restrict__ wt,
                                          int t0, ull (&acc2)[4][4],
                                          float (*xs)[16][64], float (*ws)[16][128])
{
    const int tid = threadIdx.x;
    const int tt = tid & 15;
    const int og = tid >> 4;
    float xr[4], wr[8];
    #pragma unroll
    for (int r=0;r<4;r++){ int idx=tid+r*256, i=idx>>6, t=idx&63, gt=t0+t;
        xr[r] = (gt<HWTOK) ? xn[(size_t)i*HWTOK+gt] : 0.f; }
    #pragma unroll
    for (int r=0;r<8;r++){ int idx=tid+r*256, i=idx>>7, o=idx&127;
        wr[r] = wt[i*128+o]; }
    #pragma unroll
    for (int r=0;r<4;r++){ int idx=tid+r*256; xs[0][idx>>6][idx&63]=xr[r]; }
    #pragma unroll
    for (int r=0;r<8;r++){ int idx=tid+r*256; ws[0][idx>>7][idx&127]=wr[r]; }
    __syncthreads();

    for (int s=0; s<KSTEPS; s++){
        const int b = s&1;
        if (s<KSTEPS-1){
            const int kc=(s+1)*16;
            #pragma unroll
            for (int r=0;r<4;r++){ int idx=tid+r*256, i=idx>>6, t=idx&63, gt=t0+t;
                xr[r] = (gt<HWTOK) ? xn[(size_t)(kc+i)*HWTOK+gt] : 0.f; }
            #pragma unroll
            for (int r=0;r<8;r++){ int idx=tid+r*256, i=idx>>7, o=idx&127;
                wr[r] = wt[(kc+i)*128+o]; }
        }
        #pragma unroll
        for (int i=0;i<16;i++){
            float4 xv = *(const float4*)&xs[b][i][tt*4];
            ull xb[4] = {pack1(xv.x), pack1(xv.y), pack1(xv.z), pack1(xv.w)};
            ulonglong2 w0 = *(const ulonglong2*)&ws[b][i][og*8];
            ulonglong2 w1 = *(const ulonglong2*)&ws[b][i][og*8+4];
            ull wp[4] = {w0.x, w0.y, w1.x, w1.y};
            #pragma unroll
            for (int p=0;p<4;p++)
                #pragma unroll
                for (int t=0;t<4;t++)
                    acc2[p][t] = fma2r(xb[t], wp[p], acc2[p][t]);
        }
        if (s<KSTEPS-1){
            const int nb = b^1;
            #pragma unroll
            for (int r=0;r<4;r++){ int idx=tid+r*256; xs[nb][idx>>6][idx&63]=xr[r]; }
            #pragma unroll
            for (int r=0;r<8;r++){ int idx=tid+r*256; ws[nb][idx>>7][idx&127]=wr[r]; }
        }
        __syncthreads();
    }
}

// ---------------- in-proj: x -> tanh -> padded g_xtp ----------------
__global__ __launch_bounds__(256) void inproj_kernel(const float* __restrict__ x,
                                                     const float* __restrict__ bias)
{
    __shared__ float xs[2][16][64];
    __shared__ float ws[2][16][128];
    const int n  = blockIdx.y;
    const int t0 = blockIdx.x * 64;
    const int tt = threadIdx.x & 15;
    const int og = threadIdx.x >> 4;
    ull acc2[4][4];
    #pragma unroll
    for (int p=0;p<4;p++) for (int t=0;t<4;t++) acc2[p][t] = 0ull;
    gemm_core<8>(x + (size_t)n*128*HWTOK, g_wt_in, t0, acc2, xs, ws);
    #pragma unroll
    for (int p=0;p<4;p++){
        int oc0 = og*8 + 2*p;
        float b0 = bias[oc0], b1 = bias[oc0+1];
        #pragma unroll
        for (int t=0;t<4;t++){
            int gt = t0 + tt*4 + t;
            if (gt >= HWTOK) continue;
            float v0, v1; unpack2(acc2[p][t], v0, v1);
            int y = gt/WW, xc = gt - y*WW;
            size_t base = (((size_t)n*RCH)*HP + (y+1))*HP + (xc+1);
            g_xtp[base + (size_t)oc0*HP*HP]     = tanh_fast(v0 + b0);
            g_xtp[base + (size_t)(oc0+1)*HP*HP] = tanh_fast(v1 + b1);
        }
    }
}

// ---------------- out-proj ----------------
__global__ __launch_bounds__(256) void outproj_kernel(const float* __restrict__ bias,
                                                      float* __restrict__ outx)
{
    __shared__ float xs[2][16][64];
    __shared__ float ws[2][16][128];
    const int n  = blockIdx.y;
    const int t0 = blockIdx.x * 64;
    const int tt = threadIdx.x & 15;
    const int og = threadIdx.x >> 4;
    ull acc2[4][4];
    #pragma unroll
    for (int p=0;p<4;p++) for (int t=0;t<4;t++) acc2[p][t] = 0ull;
    gemm_core<8>(g_h + (size_t)n*128*HWTOK, g_wt_out, t0, acc2, xs, ws);
    #pragma unroll
    for (int p=0;p<4;p++){
        int oc0 = og*8 + 2*p;
        float b0 = bias[oc0], b1 = bias[oc0+1];
        #pragma unroll
        for (int t=0;t<4;t++){
            int gt = t0 + tt*4 + t;
            if (gt >= HWTOK) continue;
            float v0, v1; unpack2(acc2[p][t], v0, v1);
            outx[((size_t)n*RCH+oc0)*HWTOK+gt]   = v0 + b0;
            outx[((size_t)n*RCH+oc0+1)*HWTOK+gt] = v1 + b1;
        }
    }
}

// ---------------- LSTM activation ----------------
#define ACT_N4 (NIMG*RCH*(HWTOK/4))
__global__ __launch_bounds__(256) void lstm_act_kernel(const float* __restrict__ bi,
                                                       const float* __restrict__ bg,
                                                       const float* __restrict__ bo)
{
    int i4 = blockIdx.x*256 + threadIdx.x;
    if (i4 >= ACT_N4) return;
    int oc = (i4 / (HWTOK/4)) & 127;
    float bbi = bi[oc], bbg = bg[oc], bbo = bo[oc];
    float4 pi = ((const float4*)g_pre[0])[i4];
    float4 pg = ((const float4*)g_pre[1])[i4];
    float4 po = ((const float4*)g_pre[2])[i4];
    float4 r;
    r.x = sigmoid_fast(po.x+bbo) * tanh_fast(sigmoid_fast(pi.x+bbi) * tanh_fast(pg.x+bbg));
    r.y = sigmoid_fast(po.y+bbo) * tanh_fast(sigmoid_fast(pi.y+bbi) * tanh_fast(pg.y+bbg));
    r.z = sigmoid_fast(po.z+bbo) * tanh_fast(sigmoid_fast(pi.z+bbi) * tanh_fast(pg.z+bbg));
    r.w = sigmoid_fast(po.w+bbo) * tanh_fast(sigmoid_fast(pi.w+bbi) * tanh_fast(pg.w+bbg));
    ((float4*)g_h)[i4] = r;
}

// ---------------- conv3x3 (2 output rows/block, double-buffered) ----------------
__global__ void conv3x3_kernel(const float* __restrict__ bias)
{
    __shared__ float xs[2][8][4][40];
    __shared__ float ws[2][8][9][128];
    const int n  = blockIdx.y;
    const int y0 = blockIdx.x*2;
    const int tid = threadIdx.x;        // 288 threads
    const int tg = tid % 9;
    const int og = tid / 9;
    ull acc2[2][2][4];
    #pragma unroll
    for (int yr=0;yr<2;yr++) for (int p=0;p<2;p++) for (int t=0;t<4;t++) acc2[yr][p][t]=0ull;

    const float* xp = g_xtp + (size_t)n*RCH*HP*HP;
    float xr[5]; float4 wr[8];

    #pragma unroll
    for (int r=0;r<5;r++){
        int idx = tid + r*288;
        if (idx < 1216){
            int ci = idx/152, rem = idx - ci*152, dy = rem/38, cx = rem - dy*38;
            xr[r] = xp[(size_t)ci*HP*HP + (y0+dy)*HP + cx];
        }
    }
    #pragma unroll
    for (int r=0;r<8;r++) wr[r] = ((const float4*)g_wt_conv)[tid + r*288];
    #pragma unroll
    for (int r=0;r<5;r++){
        int idx = tid + r*288;
        if (idx < 1216){
            int ci = idx/152, rem = idx - ci*152, dy = rem/38, cx = rem - dy*38;
            xs[0][ci][dy][cx] = xr[r];
        }
    }
    #pragma unroll
    for (int r=0;r<8;r++) ((float4*)ws[0])[tid + r*288] = wr[r];
    __syncthreads();

    for (int s=0; s<16; s++){
        const int b = s&1;
        if (s<15){
            const int kc=(s+1)*8;
            #pragma unroll
            for (int r=0;r<5;r++){
                int idx = tid + r*288;
                if (idx < 1216){
                    int ci = idx/152, rem = idx - ci*152, dy = rem/38, cx = rem - dy*38;
                    xr[r] = xp[(size_t)(kc+ci)*HP*HP + (y0+dy)*HP + cx];
                }
            }
            #pragma unroll
            for (int r=0;r<8;r++) wr[r] = ((const float4*)(g_wt_conv + kc*1152))[tid + r*288];
        }
        #pragma unroll
        for (int i=0;i<8;i++){
            ull xb[4][6];
            #pragma unroll
            for (int dy=0; dy<4; dy++){
                float4 x4 = *(const float4*)&xs[b][i][dy][tg*4];
                float2 x2 = *(const float2*)&xs[b][i][dy][tg*4+4];
                xb[dy][0]=pack1(x4.x); xb[dy][1]=pack1(x4.y); xb[dy][2]=pack1(x4.z);
                xb[dy][3]=pack1(x4.w); xb[dy][4]=pack1(x2.x); xb[dy][5]=pack1(x2.y);
            }
            #pragma unroll
            for (int dy=0;dy<3;dy++)
                #pragma unroll
                for (int dx=0;dx<3;dx++){
                    ulonglong2 w2 = *(const ulonglong2*)&ws[b][i][dy*3+dx][og*4];
                    #pragma unroll
                    for (int yr=0;yr<2;yr++)
                        #pragma unroll
                        for (int t=0;t<4;t++){
                            acc2[yr][0][t] = fma2r(xb[dy+yr][t+dx], w2.x, acc2[yr][0][t]);
                            acc2[yr][1][t] = fma2r(xb[dy+yr][t+dx], w2.y, acc2[yr][1][t]);
                        }
                }
        }
        if (s<15){
            const int nb = b^1;
            #pragma unroll
            for (int r=0;r<5;r++){
                int idx = tid + r*288;
                if (idx < 1216){
                    int ci = idx/152, rem = idx - ci*152, dy = rem/38, cx = rem - dy*38;
                    xs[nb][ci][dy][cx] = xr[r];
                }
            }
            #pragma unroll
            for (int r=0;r<8;r++) ((float4*)ws[nb])[tid + r*288] = wr[r];
        }
        __syncthreads();
    }

    #pragma unroll
    for (int yr=0;yr<2;yr++){
        int y = y0 + yr;
        #pragma unroll
        for (int p=0;p<2;p++){
            int oc0 = og*4 + 2*p;
            float b0 = bias[oc0], b1 = bias[oc0+1];
            #pragma unroll
            for (int t=0;t<4;t++){
                int xc = tg*4+t;
                float v0, v1; unpack2(acc2[yr][p][t], v0, v1);
                g_za[((size_t)n*256 + oc0)*HWTOK + y*WW + xc]   = v0 + b0;
                g_za[((size_t)n*256 + oc0+1)*HWTOK + y*WW + xc] = v1 + b1;
            }
        }
    }
}

// ---------------- attention split-K: each CTA = (q-half, j-half, head) ----------------
#define ATTN_THREADS 352
#define ATTN_ACT 324
#define JHALF 648
#define ATTN_SMEM (2*JHALF*HEADC*4)

__global__ __launch_bounds__(ATTN_THREADS,2) void attn_kernel()
{
    extern __shared__ float sm[];
    float* Ks = sm;                       // [648][16]
    float* Vs = sm + JHALF*HEADC;
    const int nh = blockIdx.y; const int n = nh >> 3; const int h = nh & 7;
    const int qh = blockIdx.x & 1;
    const int jh = blockIdx.x >> 1;
    const int j0 = jh * JHALF;
    const int tid = threadIdx.x;
    const float* kp = g_k + ((size_t)n*RCH + h*HEADC)*HWTOK + j0;
    const float* vp = g_v + ((size_t)n*RCH + h*HEADC)*HWTOK + j0;
    #pragma unroll
    for (int c=0;c<HEADC;c++){
        for (int j=tid;j<JHALF;j+=ATTN_THREADS){
            Ks[j*HEADC+c] = kp[(size_t)c*HWTOK+j];
            Vs[j*HEADC+c] = vp[(size_t)c*HWTOK+j];
        }
    }
    __syncthreads();
    if (tid >= ATTN_ACT) return;

    const int qa = qh*648 + tid;
    const int qb = qa + ATTN_ACT;
    const float* qp = g_q + ((size_t)n*RCH + h*HEADC)*HWTOK;
    ull q2[2][8], a2[2][8]; float l[2];
    #pragma unroll
    for (int u=0;u<2;u++){
        int q = (u==0) ? qa : qb;
        #pragma unroll
        for (int p=0;p<8;p++){
            q2[u][p] = pack2(qp[(size_t)(2*p)*HWTOK+q]*LOG2E,
                             qp[(size_t)(2*p+1)*HWTOK+q]*LOG2E);
            a2[u][p] = 0ull;
        }
        l[u] = 0.f;
    }
    #pragma unroll 2
    for (int j=0;j<JHALF;j++){
        const ulonglong2* kr = (const ulonglong2*)(Ks + j*HEADC);
        ulonglong2 k0 = kr[0], k1 = kr[1], k2 = kr[2], k3 = kr[3];
        float e[2];
        #pragma unroll
        for (int u=0;u<2;u++){
            ull s = mul2(q2[u][0], k0.x);
            s = fma2r(q2[u][1], k0.y, s);
            s = fma2r(q2[u][2], k1.x, s);
            s = fma2r(q2[u][3], k1.y, s);
            s = fma2r(q2[u][4], k2.x, s);
            s = fma2r(q2[u][5], k2.y, s);
            s = fma2r(q2[u][6], k3.x, s);
            s = fma2r(q2[u][7], k3.y, s);
            float s0, s1; unpack2(s, s0, s1);
            e[u] = ex2_fast(s0 + s1);
            l[u] += e[u];
        }
        const ulonglong2* vr = (const ulonglong2*)(Vs + j*HEADC);
        ulonglong2 v0 = vr[0], v1 = vr[1], v2 = vr[2], v3 = vr[3];
        ull vv[8] = {v0.x,v0.y,v1.x,v1.y,v2.x,v2.y,v3.x,v3.y};
        #pragma unroll
        for (int u=0;u<2;u++){
            ull eb = pack1(e[u]);
            #pragma unroll
            for (int p=0;p<8;p++) a2[u][p] = fma2r(eb, vv[p], a2[u][p]);
        }
    }
    float* pp = g_pat[jh] + (size_t)nh*HEADC*HWTOK;
    float* lp = g_plen[jh] + (size_t)nh*HWTOK;
    #pragma unroll
    for (int u=0;u<2;u++){
        int q = (u==0) ? qa : qb;
        lp[q] = l[u];
        #pragma unroll
        for (int p=0;p<8;p++){
            float lo, hi; unpack2(a2[u][p], lo, hi);
            pp[(size_t)(2*p)*HWTOK + q]   = lo;
            pp[(size_t)(2*p+1)*HWTOK + q] = hi;
        }
    }
}

// ---------------- attention merge: za_a = (pA+pB)/(lA+lB) ----------------
#define MERGE_N4 (NIMG*NHEAD*HEADC*(HWTOK/4))
__global__ __launch_bounds__(256) void attn_merge_kernel()
{
    int i4 = blockIdx.x*256 + threadIdx.x;
    if (i4 >= MERGE_N4) return;
    int qq = i4 % (HWTOK/4);
    int nhc = i4 / (HWTOK/4);          // nh*16 + c
    int nh = nhc >> 4;
    float4 pa = ((const float4*)g_pat[0])[i4];
    float4 pb = ((const float4*)g_pat[1])[i4];
    int li = nh*(HWTOK/4) + qq;
    float4 la = ((const float4*)g_plen[0])[li];
    float4 lb = ((const float4*)g_plen[1])[li];
    float4 r;
    r.x = (pa.x + pb.x) / (la.x + lb.x);
    r.y = (pa.y + pb.y) / (la.y + lb.y);
    r.z = (pa.z + pb.z) / (la.z + lb.z);
    r.w = (pa.w + pb.w) / (la.w + lb.w);
    int n = nh >> 3, h = nh & 7, c = nhc & 15;
    ((float4*)(g_za + ((size_t)n*256 + 128 + h*HEADC + c)*HWTOK))[qq] = r;
}

// ---------------- launch ----------------
extern "C" void kernel_launch(void* const* d_in, const int* in_sizes, int n_in,
                              void* d_out, int out_size)
{
    const float* x      = (const float*)d_in[0];
    const float* w_in   = (const float*)d_in[1];
    const float* b_in   = (const float*)d_in[2];
    const float* w_conv = (const float*)d_in[3];
    const float* b_conv = (const float*)d_in[4];
    const float* wq     = (const float*)d_in[5];
    const float* wk     = (const float*)d_in[6];
    const float* wv     = (const float*)d_in[7];
    const float* w_i    = (const float*)d_in[8];
    const float* b_i    = (const float*)d_in[9];
    // d_in[10], d_in[11]: w_f/b_f unused (first timestep: f*c0 == 0)
    const float* w_g    = (const float*)d_in[12];
    const float* b_g    = (const float*)d_in[13];
    const float* w_o    = (const float*)d_in[14];
    const float* b_o    = (const float*)d_in[15];
    const float* w_out  = (const float*)d_in[16];
    const float* b_out  = (const float*)d_in[17];
    float* out = (float*)d_out;

    cudaFuncSetAttribute(attn_kernel, cudaFuncAttributeMaxDynamicSharedMemorySize, ATTN_SMEM);

    repack_all<<<1280,256>>>(w_in, wq, wk, wv, w_i, w_g, w_o, w_out, w_conv);

    inproj_kernel<<<dim3(21,NIMG),256>>>(x, b_in);                   // -> g_xtp
    conv3x3_kernel<<<dim3(18,NIMG),288>>>(b_conv);                   // -> g_za[:, :128]
    qkv_kernel<<<dim3(11,NIMG,3),256>>>();                           // -> g_q/g_k/g_v
    attn_kernel<<<dim3(4, NIMG*NHEAD), ATTN_THREADS, ATTN_SMEM>>>(); // -> g_pat/g_plen
    attn_merge_kernel<<<(MERGE_N4+255)/256,256>>>();                 // -> g_za[:,128:]
    gates_gemm_kernel<<<dim3(11,NIMG,3),256>>>();                    // -> g_pre
    lstm_act_kernel<<<(ACT_N4+255)/256,256>>>(b_i, b_g, b_o);        // -> g_h
    outproj_kernel<<<dim3(21,NIMG),256>>>(b_out, out);               // -> d_out
}

// round 6
// speedup vs baseline: 1.5097x; 1.5097x over previous
#include <cuda_runtime.h>
#include <math.h>

#define NIMG 8
#define HH 36
#define WW 36
#define HWTOK 1296
#define HP 38
#define RCH 128
#define NHEAD 8
#define HEADC 16
#define LOG2E 1.44269504088896340736f

typedef unsigned long long ull;

// ---------------- scratch (device globals; zero-init at load) ----------------
__device__ float g_xtp[(size_t)NIMG*RCH*HP*HP];     // padded tanh(in-proj); borders stay 0
__device__ float g_za [(size_t)NIMG*256*HWTOK];     // [z | a]
__device__ float g_q  [(size_t)NIMG*RCH*HWTOK];
__device__ float g_k  [(size_t)NIMG*RCH*HWTOK];
__device__ float g_v  [(size_t)NIMG*RCH*HWTOK];
__device__ float g_h  [(size_t)NIMG*RCH*HWTOK];
__device__ float g_pre[3][(size_t)NIMG*RCH*HWTOK];  // gate pre-activations i,g,o

// transposed weights ([in][out], coalesced for GEMM smem fills)
__device__ float g_wt_in [128*128];
__device__ float g_wt_q  [128*128];
__device__ float g_wt_k  [128*128];
__device__ float g_wt_v  [128*128];
__device__ float g_wt_out[128*128];
__device__ float g_wt_i  [256*128];
__device__ float g_wt_g  [256*128];
__device__ float g_wt_o  [256*128];
__device__ float g_wt_conv[1152*128];               // [(ci*9+tap)][o], ci<128 only

// ---------------- helpers ----------------
__device__ __forceinline__ float tanh_fast(float x){
    float r; asm("tanh.approx.f32 %0, %1;" : "=f"(r) : "f"(x)); return r;
}
__device__ __forceinline__ float sigmoid_fast(float x){
    return 0.5f * tanh_fast(0.5f * x) + 0.5f;
}
__device__ __forceinline__ float ex2_fast(float x){
    float r; asm("ex2.approx.f32 %0, %1;" : "=f"(r) : "f"(x)); return r;
}
__device__ __forceinline__ ull pack2(float a, float b){
    ull r; asm("mov.b64 %0, {%1,%2};" : "=l"(r) : "f"(a), "f"(b)); return r;
}
__device__ __forceinline__ ull pack1(float a){
    ull r; asm("mov.b64 %0, {%1,%1};" : "=l"(r) : "f"(a)); return r;
}
__device__ __forceinline__ void unpack2(ull v, float& a, float& b){
    asm("mov.b64 {%0,%1}, %2;" : "=f"(a), "=f"(b) : "l"(v));
}
__device__ __forceinline__ ull mul2(ull a, ull b){
    ull d; asm("mul.rn.f32x2 %0, %1, %2;" : "=l"(d) : "l"(a), "l"(b)); return d;
}
__device__ __forceinline__ ull fma2r(ull a, ull b, ull c){
    ull d; asm("fma.rn.f32x2 %0, %1, %2, %3;" : "=l"(d) : "l"(a), "l"(b), "l"(c)); return d;
}

// ---------------- weight repack ----------------
__global__ void repack_all(const float* __restrict__ w_in, const float* __restrict__ wq,
                           const float* __restrict__ wk,   const float* __restrict__ wv,
                           const float* __restrict__ w_i,  const float* __restrict__ w_g,
                           const float* __restrict__ w_o,  const float* __restrict__ w_out,
                           const float* __restrict__ w_conv)
{
    int idx = blockIdx.x*256 + threadIdx.x;
    if (idx < 5*16384) {
        int m = idx >> 14; int r = idx & 16383; int o = r >> 7; int i = r & 127;
        float v;
        if      (m==0) v = w_in[r];
        else if (m==1) v = wq[r];
        else if (m==2) v = wk[r];
        else if (m==3) v = wv[r];
        else           v = w_out[r];
        float* d = (m==0)?g_wt_in:(m==1)?g_wt_q:(m==2)?g_wt_k:(m==3)?g_wt_v:g_wt_out;
        d[i*128+o] = v;
    } else if (idx < 5*16384 + 3*32768) {
        int r = idx - 5*16384; int m = r >> 15; int rr = r & 32767;
        int o = rr >> 8; int i = rr & 255;    // src [128][256]
        float v = (m==0) ? w_i[rr] : (m==1) ? w_g[rr] : w_o[rr];
        float* d = (m==0)?g_wt_i:(m==1)?g_wt_g:g_wt_o;
        d[i*128+o] = v;
    } else if (idx < 5*16384 + 3*32768 + 147456) {
        int r = idx - (5*16384 + 3*32768);
        int o = r / 1152; int rem = r - o*1152;         // rem = ci*9+tap, ci<128
        g_wt_conv[rem*128 + o] = w_conv[(size_t)o*2304 + rem];
    }
}

// ---------------- lean GEMM core: 64 tok x 128 out, double-buffered ----------------
template<int KSTEPS>
__device__ __forceinline__ void gemm_core(const float* __restrict__ xn,
                                          const float* __restrict__ wt,
                                          int t0, ull (&acc2)[4][4],
                                          float (*xs)[16][64], float (*ws)[16][128])
{
    const int tid = threadIdx.x;
    const int tt = tid & 15;
    const int og = tid >> 4;
    float xr[4], wr[8];
    #pragma unroll
    for (int r=0;r<4;r++){ int idx=tid+r*256, i=idx>>6, t=idx&63, gt=t0+t;
        xr[r] = (gt<HWTOK) ? xn[(size_t)i*HWTOK+gt] : 0.f; }
    #pragma unroll
    for (int r=0;r<8;r++){ int idx=tid+r*256, i=idx>>7, o=idx&127;
        wr[r] = wt[i*128+o]; }
    #pragma unroll
    for (int r=0;r<4;r++){ int idx=tid+r*256; xs[0][idx>>6][idx&63]=xr[r]; }
    #pragma unroll
    for (int r=0;r<8;r++){ int idx=tid+r*256; ws[0][idx>>7][idx&127]=wr[r]; }
    __syncthreads();

    for (int s=0; s<KSTEPS; s++){
        const int b = s&1;
        if (s<KSTEPS-1){
            const int kc=(s+1)*16;
            #pragma unroll
            for (int r=0;r<4;r++){ int idx=tid+r*256, i=idx>>6, t=idx&63, gt=t0+t;
                xr[r] = (gt<HWTOK) ? xn[(size_t)(kc+i)*HWTOK+gt] : 0.f; }
            #pragma unroll
            for (int r=0;r<8;r++){ int idx=tid+r*256, i=idx>>7, o=idx&127;
                wr[r] = wt[(kc+i)*128+o]; }
        }
        #pragma unroll
        for (int i=0;i<16;i++){
            float4 xv = *(const float4*)&xs[b][i][tt*4];
            ull xb[4] = {pack1(xv.x), pack1(xv.y), pack1(xv.z), pack1(xv.w)};
            ulonglong2 w0 = *(const ulonglong2*)&ws[b][i][og*8];
            ulonglong2 w1 = *(const ulonglong2*)&ws[b][i][og*8+4];
            ull wp[4] = {w0.x, w0.y, w1.x, w1.y};
            #pragma unroll
            for (int p=0;p<4;p++)
                #pragma unroll
                for (int t=0;t<4;t++)
                    acc2[p][t] = fma2r(xb[t], wp[p], acc2[p][t]);
        }
        if (s<KSTEPS-1){
            const int nb = b^1;
            #pragma unroll
            for (int r=0;r<4;r++){ int idx=tid+r*256; xs[nb][idx>>6][idx&63]=xr[r]; }
            #pragma unroll
            for (int r=0;r<8;r++){ int idx=tid+r*256; ws[nb][idx>>7][idx&127]=wr[r]; }
        }
        __syncthreads();
    }
}

// ---------------- in-proj: x -> tanh -> padded g_xtp ----------------
__global__ __launch_bounds__(256) void inproj_kernel(const float* __restrict__ x,
                                                     const float* __restrict__ bias)
{
    __shared__ float xs[2][16][64];
    __shared__ float ws[2][16][128];
    const int n  = blockIdx.y;
    const int t0 = blockIdx.x * 64;
    const int tt = threadIdx.x & 15;
    const int og = threadIdx.x >> 4;
    ull acc2[4][4];
    #pragma unroll
    for (int p=0;p<4;p++) for (int t=0;t<4;t++) acc2[p][t] = 0ull;
    gemm_core<8>(x + (size_t)n*128*HWTOK, g_wt_in, t0, acc2, xs, ws);
    #pragma unroll
    for (int p=0;p<4;p++){
        int oc0 = og*8 + 2*p;
        float b0 = bias[oc0], b1 = bias[oc0+1];
        #pragma unroll
        for (int t=0;t<4;t++){
            int gt = t0 + tt*4 + t;
            if (gt >= HWTOK) continue;
            float v0, v1; unpack2(acc2[p][t], v0, v1);
            int y = gt/WW, xc = gt - y*WW;
            size_t base = (((size_t)n*RCH)*HP + (y+1))*HP + (xc+1);
            g_xtp[base + (size_t)oc0*HP*HP]     = tanh_fast(v0 + b0);
            g_xtp[base + (size_t)(oc0+1)*HP*HP] = tanh_fast(v1 + b1);
        }
    }
}

// ---------------- qkv: z selects matrix; raw store ----------------
__global__ __launch_bounds__(256) void qkv_kernel()
{
    __shared__ float xs[2][16][64];
    __shared__ float ws[2][16][128];
    const int n  = blockIdx.y;
    const int z  = blockIdx.z;
    const int t0 = blockIdx.x * 64;
    const int tt = threadIdx.x & 15;
    const int og = threadIdx.x >> 4;
    const float* wt = (z==0) ? g_wt_q : (z==1) ? g_wt_k : g_wt_v;
    float* dst      = (z==0) ? g_q    : (z==1) ? g_k    : g_v;
    ull acc2[4][4];
    #pragma unroll
    for (int p=0;p<4;p++) for (int t=0;t<4;t++) acc2[p][t] = 0ull;
    gemm_core<8>(g_za + (size_t)n*256*HWTOK, wt, t0, acc2, xs, ws);
    #pragma unroll
    for (int p=0;p<4;p++){
        int oc0 = og*8 + 2*p;
        #pragma unroll
        for (int t=0;t<4;t++){
            int gt = t0 + tt*4 + t;
            if (gt >= HWTOK) continue;
            float v0, v1; unpack2(acc2[p][t], v0, v1);
            dst[((size_t)n*RCH+oc0)*HWTOK+gt]   = v0;
            dst[((size_t)n*RCH+oc0+1)*HWTOK+gt] = v1;
        }
    }
}

// ---------------- gates GEMM: z in {i,g,o}; raw store to g_pre ----------------
__global__ __launch_bounds__(256) void gates_gemm_kernel()
{
    __shared__ float xs[2][16][64];
    __shared__ float ws[2][16][128];
    const int n  = blockIdx.y;
    const int z  = blockIdx.z;
    const int t0 = blockIdx.x * 64;
    const int tt = threadIdx.x & 15;
    const int og = threadIdx.x >> 4;
    const float* wt = (z==0) ? g_wt_i : (z==1) ? g_wt_g : g_wt_o;
    float* dst = g_pre[z];
    ull acc2[4][4];
    #pragma unroll
    for (int p=0;p<4;p++) for (int t=0;t<4;t++) acc2[p][t] = 0ull;
    gemm_core<16>(g_za + (size_t)n*256*HWTOK, wt, t0, acc2, xs, ws);
    #pragma unroll
    for (int p=0;p<4;p++){
        int oc0 = og*8 + 2*p;
        #pragma unroll
        for (int t=0;t<4;t++){
            int gt = t0 + tt*4 + t;
            if (gt >= HWTOK) continue;
            float v0, v1; unpack2(acc2[p][t], v0, v1);
            dst[((size_t)n*RCH+oc0)*HWTOK+gt]   = v0;
            dst[((size_t)n*RCH+oc0+1)*HWTOK+gt] = v1;
        }
    }
}

// ---------------- LSTM activation: h = sigm(o) * tanh(sigm(i)*tanh(g)) ----------------
#define ACT_N4 (NIMG*RCH*(HWTOK/4))
__global__ __launch_bounds__(256) void lstm_act_kernel(const float* __restrict__ bi,
                                                       const float* __restrict__ bg,
                                                       const float* __restrict__ bo)
{
    int i4 = blockIdx.x*256 + threadIdx.x;
    if (i4 >= ACT_N4) return;
    int oc = (i4 / (HWTOK/4)) & 127;
    float bbi = bi[oc], bbg = bg[oc], bbo = bo[oc];
    float4 pi = ((const float4*)g_pre[0])[i4];
    float4 pg = ((const float4*)g_pre[1])[i4];
    float4 po = ((const float4*)g_pre[2])[i4];
    float4 r;
    r.x = sigmoid_fast(po.x+bbo) * tanh_fast(sigmoid_fast(pi.x+bbi) * tanh_fast(pg.x+bbg));
    r.y = sigmoid_fast(po.y+bbo) * tanh_fast(sigmoid_fast(pi.y+bbi) * tanh_fast(pg.y+bbg));
    r.z = sigmoid_fast(po.z+bbo) * tanh_fast(sigmoid_fast(pi.z+bbi) * tanh_fast(pg.z+bbg));
    r.w = sigmoid_fast(po.w+bbo) * tanh_fast(sigmoid_fast(pi.w+bbi) * tanh_fast(pg.w+bbg));
    ((float4*)g_h)[i4] = r;
}

// ---------------- out-proj ----------------
__global__ __launch_bounds__(256) void outproj_kernel(const float* __restrict__ bias,
                                                      float* __restrict__ outx)
{
    __shared__ float xs[2][16][64];
    __shared__ float ws[2][16][128];
    const int n  = blockIdx.y;
    const int t0 = blockIdx.x * 64;
    const int tt = threadIdx.x & 15;
    const int og = threadIdx.x >> 4;
    ull acc2[4][4];
    #pragma unroll
    for (int p=0;p<4;p++) for (int t=0;t<4;t++) acc2[p][t] = 0ull;
    gemm_core<8>(g_h + (size_t)n*128*HWTOK, g_wt_out, t0, acc2, xs, ws);
    #pragma unroll
    for (int p=0;p<4;p++){
        int oc0 = og*8 + 2*p;
        float b0 = bias[oc0], b1 = bias[oc0+1];
        #pragma unroll
        for (int t=0;t<4;t++){
            int gt = t0 + tt*4 + t;
            if (gt >= HWTOK) continue;
            float v0, v1; unpack2(acc2[p][t], v0, v1);
            outx[((size_t)n*RCH+oc0)*HWTOK+gt]   = v0 + b0;
            outx[((size_t)n*RCH+oc0+1)*HWTOK+gt] = v1 + b1;
        }
    }
}

// ---------------- conv3x3 (2 output rows/block, double-buffered) ----------------
__global__ void conv3x3_kernel(const float* __restrict__ bias)
{
    __shared__ float xs[2][8][4][40];
    __shared__ float ws[2][8][9][128];
    const int n  = blockIdx.y;
    const int y0 = blockIdx.x*2;
    const int tid = threadIdx.x;        // 288 threads
    const int tg = tid % 9;
    const int og = tid / 9;
    ull acc2[2][2][4];
    #pragma unroll
    for (int yr=0;yr<2;yr++) for (int p=0;p<2;p++) for (int t=0;t<4;t++) acc2[yr][p][t]=0ull;

    const float* xp = g_xtp + (size_t)n*RCH*HP*HP;
    float xr[5]; float4 wr[8];

    #pragma unroll
    for (int r=0;r<5;r++){
        int idx = tid + r*288;
        if (idx < 1216){
            int ci = idx/152, rem = idx - ci*152, dy = rem/38, cx = rem - dy*38;
            xr[r] = xp[(size_t)ci*HP*HP + (y0+dy)*HP + cx];
        }
    }
    #pragma unroll
    for (int r=0;r<8;r++) wr[r] = ((const float4*)g_wt_conv)[tid + r*288];
    #pragma unroll
    for (int r=0;r<5;r++){
        int idx = tid + r*288;
        if (idx < 1216){
            int ci = idx/152, rem = idx - ci*152, dy = rem/38, cx = rem - dy*38;
            xs[0][ci][dy][cx] = xr[r];
        }
    }
    #pragma unroll
    for (int r=0;r<8;r++) ((float4*)ws[0])[tid + r*288] = wr[r];
    __syncthreads();

    for (int s=0; s<16; s++){
        const int b = s&1;
        if (s<15){
            const int kc=(s+1)*8;
            #pragma unroll
            for (int r=0;r<5;r++){
                int idx = tid + r*288;
                if (idx < 1216){
                    int ci = idx/152, rem = idx - ci*152, dy = rem/38, cx = rem - dy*38;
                    xr[r] = xp[(size_t)(kc+ci)*HP*HP + (y0+dy)*HP + cx];
                }
            }
            #pragma unroll
            for (int r=0;r<8;r++) wr[r] = ((const float4*)(g_wt_conv + kc*1152))[tid + r*288];
        }
        #pragma unroll
        for (int i=0;i<8;i++){
            ull xb[4][6];
            #pragma unroll
            for (int dy=0; dy<4; dy++){
                float4 x4 = *(const float4*)&xs[b][i][dy][tg*4];
                float2 x2 = *(const float2*)&xs[b][i][dy][tg*4+4];
                xb[dy][0]=pack1(x4.x); xb[dy][1]=pack1(x4.y); xb[dy][2]=pack1(x4.z);
                xb[dy][3]=pack1(x4.w); xb[dy][4]=pack1(x2.x); xb[dy][5]=pack1(x2.y);
            }
            #pragma unroll
            for (int dy=0;dy<3;dy++)
                #pragma unroll
                for (int dx=0;dx<3;dx++){
                    ulonglong2 w2 = *(const ulonglong2*)&ws[b][i][dy*3+dx][og*4];
                    #pragma unroll
                    for (int yr=0;yr<2;yr++)
                        #pragma unroll
                        for (int t=0;t<4;t++){
                            acc2[yr][0][t] = fma2r(xb[dy+yr][t+dx], w2.x, acc2[yr][0][t]);
                            acc2[yr][1][t] = fma2r(xb[dy+yr][t+dx], w2.y, acc2[yr][1][t]);
                        }
                }
        }
        if (s<15){
            const int nb = b^1;
            #pragma unroll
            for (int r=0;r<5;r++){
                int idx = tid + r*288;
                if (idx < 1216){
                    int ci = idx/152, rem = idx - ci*152, dy = rem/38, cx = rem - dy*38;
                    xs[nb][ci][dy][cx] = xr[r];
                }
            }
            #pragma unroll
            for (int r=0;r<8;r++) ((float4*)ws[nb])[tid + r*288] = wr[r];
        }
        __syncthreads();
    }

    #pragma unroll
    for (int yr=0;yr<2;yr++){
        int y = y0 + yr;
        #pragma unroll
        for (int p=0;p<2;p++){
            int oc0 = og*4 + 2*p;
            float b0 = bias[oc0], b1 = bias[oc0+1];
            #pragma unroll
            for (int t=0;t<4;t++){
                int xc = tg*4+t;
                float v0, v1; unpack2(acc2[yr][p][t], v0, v1);
                g_za[((size_t)n*256 + oc0)*HWTOK + y*WW + xc]   = v0 + b0;
                g_za[((size_t)n*256 + oc0+1)*HWTOK + y*WW + xc] = v1 + b1;
            }
        }
    }
}

// ---------------- attention: K,V smem-resident, 21 warps, 1 q/thread ----------------
#define ATTN_THREADS 672
#define ATTN_ACT 648
#define ATTN_SMEM (2*HWTOK*HEADC*4)

__global__ void attn_kernel()
{
    extern __shared__ float sm[];
    float* Ks = sm;                       // [1296][16]
    float* Vs = sm + HWTOK*HEADC;
    const int nh = blockIdx.y; const int n = nh >> 3; const int h = nh & 7;
    const int tid = threadIdx.x;
    const float* kp = g_k + ((size_t)n*RCH + h*HEADC)*HWTOK;
    const float* vp = g_v + ((size_t)n*RCH + h*HEADC)*HWTOK;
    #pragma unroll
    for (int c=0;c<HEADC;c++){
        for (int j=tid;j<HWTOK;j+=ATTN_THREADS){
            Ks[j*HEADC+c] = kp[(size_t)c*HWTOK+j];
            Vs[j*HEADC+c] = vp[(size_t)c*HWTOK+j];
        }
    }
    __syncthreads();
    if (tid >= ATTN_ACT) return;

    const int q = blockIdx.x*ATTN_ACT + tid;
    const float* qp = g_q + ((size_t)n*RCH + h*HEADC)*HWTOK;
    ull q2[8], a2[8];
    #pragma unroll
    for (int p=0;p<8;p++){
        q2[p] = pack2(qp[(size_t)(2*p)*HWTOK+q]*LOG2E,
                      qp[(size_t)(2*p+1)*HWTOK+q]*LOG2E);
        a2[p] = 0ull;
    }
    float l = 0.f;
    #pragma unroll 2
    for (int j=0;j<HWTOK;j++){
        const ulonglong2* kr = (const ulonglong2*)(Ks + j*HEADC);
        ulonglong2 k0 = kr[0], k1 = kr[1], k2 = kr[2], k3 = kr[3];
        ull sA = mul2(q2[0], k0.x);
        ull sB = mul2(q2[1], k0.y);
        sA = fma2r(q2[2], k1.x, sA);
        sB = fma2r(q2[3], k1.y, sB);
        sA = fma2r(q2[4], k2.x, sA);
        sB = fma2r(q2[5], k2.y, sB);
        sA = fma2r(q2[6], k3.x, sA);
        sB = fma2r(q2[7], k3.y, sB);
        float sa0, sa1, sb0, sb1;
        unpack2(sA, sa0, sa1); unpack2(sB, sb0, sb1);
        float e = ex2_fast((sa0 + sa1) + (sb0 + sb1));
        l += e;
        ull eb = pack1(e);
        const ulonglong2* vr = (const ulonglong2*)(Vs + j*HEADC);
        ulonglong2 v0 = vr[0], v1 = vr[1], v2 = vr[2], v3 = vr[3];
        a2[0] = fma2r(eb, v0.x, a2[0]);
        a2[1] = fma2r(eb, v0.y, a2[1]);
        a2[2] = fma2r(eb, v1.x, a2[2]);
        a2[3] = fma2r(eb, v1.y, a2[3]);
        a2[4] = fma2r(eb, v2.x, a2[4]);
        a2[5] = fma2r(eb, v2.y, a2[5]);
        a2[6] = fma2r(eb, v3.x, a2[6]);
        a2[7] = fma2r(eb, v3.y, a2[7]);
    }
    float inv = 1.f / l;
    float* ap = g_za + ((size_t)n*256 + 128 + h*HEADC)*HWTOK + q;
    #pragma unroll
    for (int p=0;p<8;p++){
        float lo, hi; unpack2(a2[p], lo, hi);
        ap[(size_t)(2*p)*HWTOK]   = lo*inv;
        ap[(size_t)(2*p+1)*HWTOK] = hi*inv;
    }
}

// ---------------- launch ----------------
extern "C" void kernel_launch(void* const* d_in, const int* in_sizes, int n_in,
                              void* d_out, int out_size)
{
    const float* x      = (const float*)d_in[0];
    const float* w_in   = (const float*)d_in[1];
    const float* b_in   = (const float*)d_in[2];
    const float* w_conv = (const float*)d_in[3];
    const float* b_conv = (const float*)d_in[4];
    const float* wq     = (const float*)d_in[5];
    const float* wk     = (const float*)d_in[6];
    const float* wv     = (const float*)d_in[7];
    const float* w_i    = (const float*)d_in[8];
    const float* b_i    = (const float*)d_in[9];
    // d_in[10], d_in[11]: w_f/b_f unused (first timestep: f*c0 == 0)
    const float* w_g    = (const float*)d_in[12];
    const float* b_g    = (const float*)d_in[13];
    const float* w_o    = (const float*)d_in[14];
    const float* b_o    = (const float*)d_in[15];
    const float* w_out  = (const float*)d_in[16];
    const float* b_out  = (const float*)d_in[17];
    float* out = (float*)d_out;

    cudaFuncSetAttribute(attn_kernel, cudaFuncAttributeMaxDynamicSharedMemorySize, ATTN_SMEM);

    repack_all<<<1280,256>>>(w_in, wq, wk, wv, w_i, w_g, w_o, w_out, w_conv);

    inproj_kernel<<<dim3(21,NIMG),256>>>(x, b_in);                   // -> g_xtp
    conv3x3_kernel<<<dim3(18,NIMG),288>>>(b_conv);                   // -> g_za[:, :128]
    qkv_kernel<<<dim3(21,NIMG,3),256>>>();                           // -> g_q/g_k/g_v
    attn_kernel<<<dim3(2, NIMG*NHEAD), ATTN_THREADS, ATTN_SMEM>>>(); // -> g_za[:,128:]
    gates_gemm_kernel<<<dim3(21,NIMG,3),256>>>();                    // -> g_pre
    lstm_act_kernel<<<(ACT_N4+255)/256,256>>>(b_i, b_g, b_o);        // -> g_h
    outproj_kernel<<<dim3(21,NIMG),256>>>(b_out, out);               // -> d_out
}

// round 9
// speedup vs baseline: 1.6788x; 1.1120x over previous
#include <cuda_runtime.h>
#include <stdint.h>
#include <math.h>

#define NIMG 8
#define HH 36
#define WW 36
#define HWTOK 1296
#define HP 38
#define RCH 128
#define NHEAD 8
#define HEADC 16
#define LOG2E 1.44269504088896340736f

typedef unsigned long long ull;

// ---------------- scratch (device globals; zero-init at load) ----------------
__device__ float g_xtp[(size_t)NIMG*RCH*HP*HP];     // padded tanh(in-proj); borders stay 0
__device__ float g_za [(size_t)NIMG*256*HWTOK];     // [z | a]
__device__ float g_q  [(size_t)NIMG*RCH*HWTOK];
__device__ float g_k  [(size_t)NIMG*RCH*HWTOK];
__device__ float g_v  [(size_t)NIMG*RCH*HWTOK];
__device__ float g_h  [(size_t)NIMG*RCH*HWTOK];
__device__ float g_pre[3][(size_t)NIMG*RCH*HWTOK];  // gate pre-activations i,g,o

// transposed weights ([in][out], coalesced for GEMM smem fills)
__device__ float g_wt_in [128*128];
__device__ float g_wt_q  [128*128];
__device__ float g_wt_k  [128*128];
__device__ float g_wt_v  [128*128];
__device__ float g_wt_out[128*128];
__device__ float g_wt_i  [256*128];
__device__ float g_wt_g  [256*128];
__device__ float g_wt_o  [256*128];
__device__ float g_wt_conv[1152*128];               // [(ci*9+tap)][o], ci<128 only

// ---------------- helpers ----------------
__device__ __forceinline__ float tanh_fast(float x){
    float r; asm("tanh.approx.f32 %0, %1;" : "=f"(r) : "f"(x)); return r;
}
__device__ __forceinline__ float sigmoid_fast(float x){
    return 0.5f * tanh_fast(0.5f * x) + 0.5f;
}
__device__ __forceinline__ float ex2_fast(float x){
    float r; asm("ex2.approx.f32 %0, %1;" : "=f"(r) : "f"(x)); return r;
}
__device__ __forceinline__ ull pack2(float a, float b){
    ull r; asm("mov.b64 %0, {%1,%2};" : "=l"(r) : "f"(a), "f"(b)); return r;
}
__device__ __forceinline__ ull pack1(float a){
    ull r; asm("mov.b64 %0, {%1,%1};" : "=l"(r) : "f"(a)); return r;
}
__device__ __forceinline__ void unpack2(ull v, float& a, float& b){
    asm("mov.b64 {%0,%1}, %2;" : "=f"(a), "=f"(b) : "l"(v));
}
__device__ __forceinline__ ull mul2(ull a, ull b){
    ull d; asm("mul.rn.f32x2 %0, %1, %2;" : "=l"(d) : "l"(a), "l"(b)); return d;
}
__device__ __forceinline__ ull fma2r(ull a, ull b, ull c){
    ull d; asm("fma.rn.f32x2 %0, %1, %2, %3;" : "=l"(d) : "l"(a), "l"(b), "l"(c)); return d;
}
__device__ __forceinline__ void cpasync16(void* smem_dst, const void* gmem_src, bool pred){
    unsigned int dst = (unsigned int)__cvta_generic_to_shared(smem_dst);
    int sz = pred ? 16 : 0;
    asm volatile("cp.async.cg.shared.global [%0], [%1], 16, %2;"
                 :: "r"(dst), "l"(gmem_src), "r"(sz) : "memory");
}
__device__ __forceinline__ void cp_commit(){
    asm volatile("cp.async.commit_group;" ::: "memory");
}
__device__ __forceinline__ void cp_wait1(){
    asm volatile("cp.async.wait_group 1;" ::: "memory");
}

// ---------------- weight repack ----------------
__global__ void repack_all(const float* __restrict__ w_in, const float* __restrict__ wq,
                           const float* __restrict__ wk,   const float* __restrict__ wv,
                           const float* __restrict__ w_i,  const float* __restrict__ w_g,
                           const float* __restrict__ w_o,  const float* __restrict__ w_out,
                           const float* __restrict__ w_conv)
{
    int idx = blockIdx.x*256 + threadIdx.x;
    if (idx < 5*16384) {
        int m = idx >> 14; int r = idx & 16383; int o = r >> 7; int i = r & 127;
        float v;
        if      (m==0) v = w_in[r];
        else if (m==1) v = wq[r];
        else if (m==2) v = wk[r];
        else if (m==3) v = wv[r];
        else           v = w_out[r];
        float* d = (m==0)?g_wt_in:(m==1)?g_wt_q:(m==2)?g_wt_k:(m==3)?g_wt_v:g_wt_out;
        d[i*128+o] = v;
    } else if (idx < 5*16384 + 3*32768) {
        int r = idx - 5*16384; int m = r >> 15; int rr = r & 32767;
        int o = rr >> 8; int i = rr & 255;    // src [128][256]
        float v = (m==0) ? w_i[rr] : (m==1) ? w_g[rr] : w_o[rr];
        float* d = (m==0)?g_wt_i:(m==1)?g_wt_g:g_wt_o;
        d[i*128+o] = v;
    } else if (idx < 5*16384 + 3*32768 + 147456) {
        int r = idx - (5*16384 + 3*32768);
        int o = r / 1152; int rem = r - o*1152;         // rem = ci*9+tap, ci<128
        g_wt_conv[rem*128 + o] = w_conv[(size_t)o*2304 + rem];
    }
}

// ---------------- async GEMM core: 64 tok x 128 out, 3-stage cp.async ----------------
template<int KSTEPS>
__device__ __forceinline__ void gemm_core(const float* __restrict__ xn,
                                          const float* __restrict__ wt,
                                          int t0, ull (&acc2)[4][4],
                                          float (*xs)[16][64], float (*ws)[16][128])
{
    const int tid = threadIdx.x;
    const int tt = tid & 15;
    const int og = tid >> 4;
    const int xi = tid >> 4;                 // x row (k-index within slice)
    const int xq = tid & 15;                 // token quad
    const bool xok = (t0 + xq*4) < HWTOK;
    const int wi = tid >> 5;                 // w row for first half
    const int wq = tid & 31;                 // w quad

    // prologue: stages 0 and 1
    for (int st=0; st<2; st++){
        int kc = st*16;
        cpasync16(&xs[st][xi][xq*4], xn + (size_t)(kc+xi)*HWTOK + t0 + xq*4, xok);
        cpasync16(&ws[st][wi][wq*4],   wt + (size_t)(kc+wi)*128   + wq*4, true);
        cpasync16(&ws[st][wi+8][wq*4], wt + (size_t)(kc+wi+8)*128 + wq*4, true);
        cp_commit();
    }

    for (int s=0; s<KSTEPS; s++){
        cp_wait1();
        __syncthreads();
        if (s+2 < KSTEPS){
            const int st = (s+2)%3, kc = (s+2)*16;
            cpasync16(&xs[st][xi][xq*4], xn + (size_t)(kc+xi)*HWTOK + t0 + xq*4, xok);
            cpasync16(&ws[st][wi][wq*4],   wt + (size_t)(kc+wi)*128   + wq*4, true);
            cpasync16(&ws[st][wi+8][wq*4], wt + (size_t)(kc+wi+8)*128 + wq*4, true);
        }
        cp_commit();
        const int b = s%3;
        #pragma unroll
        for (int i=0;i<16;i++){
            float4 xv = *(const float4*)&xs[b][i][tt*4];
            ull xb[4] = {pack1(xv.x), pack1(xv.y), pack1(xv.z), pack1(xv.w)};
            ulonglong2 w0 = *(const ulonglong2*)&ws[b][i][og*8];
            ulonglong2 w1 = *(const ulonglong2*)&ws[b][i][og*8+4];
            ull wp[4] = {w0.x, w0.y, w1.x, w1.y};
            #pragma unroll
            for (int p=0;p<4;p++)
                #pragma unroll
                for (int t=0;t<4;t++)
                    acc2[p][t] = fma2r(xb[t], wp[p], acc2[p][t]);
        }
        __syncthreads();
    }
}

// ---------------- in-proj: x -> tanh -> padded g_xtp ----------------
__global__ __launch_bounds__(256) void inproj_kernel(const float* __restrict__ x,
                                                     const float* __restrict__ bias)
{
    __shared__ float xs[3][16][64];
    __shared__ float ws[3][16][128];
    const int n  = blockIdx.y;
    const int t0 = blockIdx.x * 64;
    const int tt = threadIdx.x & 15;
    const int og = threadIdx.x >> 4;
    ull acc2[4][4];
    #pragma unroll
    for (int p=0;p<4;p++) for (int t=0;t<4;t++) acc2[p][t] = 0ull;
    gemm_core<8>(x + (size_t)n*128*HWTOK, g_wt_in, t0, acc2, xs, ws);
    #pragma unroll
    for (int p=0;p<4;p++){
        int oc0 = og*8 + 2*p;
        float b0 = bias[oc0], b1 = bias[oc0+1];
        #pragma unroll
        for (int t=0;t<4;t++){
            int gt = t0 + tt*4 + t;
            if (gt >= HWTOK) continue;
            float v0, v1; unpack2(acc2[p][t], v0, v1);
            int y = gt/WW, xc = gt - y*WW;
            size_t base = (((size_t)n*RCH)*HP + (y+1))*HP + (xc+1);
            g_xtp[base + (size_t)oc0*HP*HP]     = tanh_fast(v0 + b0);
            g_xtp[base + (size_t)(oc0+1)*HP*HP] = tanh_fast(v1 + b1);
        }
    }
}

// ---------------- qkv: z selects matrix; raw store ----------------
__global__ __launch_bounds__(256) void qkv_kernel()
{
    __shared__ float xs[3][16][64];
    __shared__ float ws[3][16][128];
    const int n  = blockIdx.y;
    const int z  = blockIdx.z;
    const int t0 = blockIdx.x * 64;
    const int tt = threadIdx.x & 15;
    const int og = threadIdx.x >> 4;
    const float* wt = (z==0) ? g_wt_q : (z==1) ? g_wt_k : g_wt_v;
    float* dst      = (z==0) ? g_q    : (z==1) ? g_k    : g_v;
    ull acc2[4][4];
    #pragma unroll
    for (int p=0;p<4;p++) for (int t=0;t<4;t++) acc2[p][t] = 0ull;
    gemm_core<8>(g_za + (size_t)n*256*HWTOK, wt, t0, acc2, xs, ws);
    #pragma unroll
    for (int p=0;p<4;p++){
        int oc0 = og*8 + 2*p;
        #pragma unroll
        for (int t=0;t<4;t++){
            int gt = t0 + tt*4 + t;
            if (gt >= HWTOK) continue;
            float v0, v1; unpack2(acc2[p][t], v0, v1);
            dst[((size_t)n*RCH+oc0)*HWTOK+gt]   = v0;
            dst[((size_t)n*RCH+oc0+1)*HWTOK+gt] = v1;
        }
    }
}

// ---------------- gates GEMM: z in {i,g,o}; raw store to g_pre ----------------
__global__ __launch_bounds__(256) void gates_gemm_kernel()
{
    __shared__ float xs[3][16][64];
    __shared__ float ws[3][16][128];
    const int n  = blockIdx.y;
    const int z  = blockIdx.z;
    const int t0 = blockIdx.x * 64;
    const int tt = threadIdx.x & 15;
    const int og = threadIdx.x >> 4;
    const float* wt = (z==0) ? g_wt_i : (z==1) ? g_wt_g : g_wt_o;
    float* dst = g_pre[z];
    ull acc2[4][4];
    #pragma unroll
    for (int p=0;p<4;p++) for (int t=0;t<4;t++) acc2[p][t] = 0ull;
    gemm_core<16>(g_za + (size_t)n*256*HWTOK, wt, t0, acc2, xs, ws);
    #pragma unroll
    for (int p=0;p<4;p++){
        int oc0 = og*8 + 2*p;
        #pragma unroll
        for (int t=0;t<4;t++){
            int gt = t0 + tt*4 + t;
            if (gt >= HWTOK) continue;
            float v0, v1; unpack2(acc2[p][t], v0, v1);
            dst[((size_t)n*RCH+oc0)*HWTOK+gt]   = v0;
            dst[((size_t)n*RCH+oc0+1)*HWTOK+gt] = v1;
        }
    }
}

// ---------------- LSTM activation: h = sigm(o) * tanh(sigm(i)*tanh(g)) ----------------
#define ACT_N4 (NIMG*RCH*(HWTOK/4))
__global__ __launch_bounds__(256) void lstm_act_kernel(const float* __restrict__ bi,
                                                       const float* __restrict__ bg,
                                                       const float* __restrict__ bo)
{
    int i4 = blockIdx.x*256 + threadIdx.x;
    if (i4 >= ACT_N4) return;
    int oc = (i4 / (HWTOK/4)) & 127;
    float bbi = bi[oc], bbg = bg[oc], bbo = bo[oc];
    float4 pi = ((const float4*)g_pre[0])[i4];
    float4 pg = ((const float4*)g_pre[1])[i4];
    float4 po = ((const float4*)g_pre[2])[i4];
    float4 r;
    r.x = sigmoid_fast(po.x+bbo) * tanh_fast(sigmoid_fast(pi.x+bbi) * tanh_fast(pg.x+bbg));
    r.y = sigmoid_fast(po.y+bbo) * tanh_fast(sigmoid_fast(pi.y+bbi) * tanh_fast(pg.y+bbg));
    r.z = sigmoid_fast(po.z+bbo) * tanh_fast(sigmoid_fast(pi.z+bbi) * tanh_fast(pg.z+bbg));
    r.w = sigmoid_fast(po.w+bbo) * tanh_fast(sigmoid_fast(pi.w+bbi) * tanh_fast(pg.w+bbg));
    ((float4*)g_h)[i4] = r;
}

// ---------------- out-proj ----------------
__global__ __launch_bounds__(256) void outproj_kernel(const float* __restrict__ bias,
                                                      float* __restrict__ outx)
{
    __shared__ float xs[3][16][64];
    __shared__ float ws[3][16][128];
    const int n  = blockIdx.y;
    const int t0 = blockIdx.x * 64;
    const int tt = threadIdx.x & 15;
    const int og = threadIdx.x >> 4;
    ull acc2[4][4];
    #pragma unroll
    for (int p=0;p<4;p++) for (int t=0;t<4;t++) acc2[p][t] = 0ull;
    gemm_core<8>(g_h + (size_t)n*128*HWTOK, g_wt_out, t0, acc2, xs, ws);
    #pragma unroll
    for (int p=0;p<4;p++){
        int oc0 = og*8 + 2*p;
        float b0 = bias[oc0], b1 = bias[oc0+1];
        #pragma unroll
        for (int t=0;t<4;t++){
            int gt = t0 + tt*4 + t;
            if (gt >= HWTOK) continue;
            float v0, v1; unpack2(acc2[p][t], v0, v1);
            outx[((size_t)n*RCH+oc0)*HWTOK+gt]   = v0 + b0;
            outx[((size_t)n*RCH+oc0+1)*HWTOK+gt] = v1 + b1;
        }
    }
}

// ---------------- conv3x3 (2 output rows/block, double-buffered) ----------------
__global__ void conv3x3_kernel(const float* __restrict__ bias)
{
    __shared__ float xs[2][8][4][40];
    __shared__ float ws[2][8][9][128];
    const int n  = blockIdx.y;
    const int y0 = blockIdx.x*2;
    const int tid = threadIdx.x;        // 288 threads
    const int tg = tid % 9;
    const int og = tid / 9;
    ull acc2[2][2][4];
    #pragma unroll
    for (int yr=0;yr<2;yr++) for (int p=0;p<2;p++) for (int t=0;t<4;t++) acc2[yr][p][t]=0ull;

    const float* xp = g_xtp + (size_t)n*RCH*HP*HP;
    float xr[5]; float4 wr[8];

    #pragma unroll
    for (int r=0;r<5;r++){
        int idx = tid + r*288;
        if (idx < 1216){
            int ci = idx/152, rem = idx - ci*152, dy = rem/38, cx = rem - dy*38;
            xr[r] = xp[(size_t)ci*HP*HP + (y0+dy)*HP + cx];
        }
    }
    #pragma unroll
    for (int r=0;r<8;r++) wr[r] = ((const float4*)g_wt_conv)[tid + r*288];
    #pragma unroll
    for (int r=0;r<5;r++){
        int idx = tid + r*288;
        if (idx < 1216){
            int ci = idx/152, rem = idx - ci*152, dy = rem/38, cx = rem - dy*38;
            xs[0][ci][dy][cx] = xr[r];
        }
    }
    #pragma unroll
    for (int r=0;r<8;r++) ((float4*)ws[0])[tid + r*288] = wr[r];
    __syncthreads();

    for (int s=0; s<16; s++){
        const int b = s&1;
        if (s<15){
            const int kc=(s+1)*8;
            #pragma unroll
            for (int r=0;r<5;r++){
                int idx = tid + r*288;
                if (idx < 1216){
                    int ci = idx/152, rem = idx - ci*152, dy = rem/38, cx = rem - dy*38;
                    xr[r] = xp[(size_t)(kc+ci)*HP*HP + (y0+dy)*HP + cx];
                }
            }
            #pragma unroll
            for (int r=0;r<8;r++) wr[r] = ((const float4*)(g_wt_conv + kc*1152))[tid + r*288];
        }
        #pragma unroll
        for (int i=0;i<8;i++){
            ull xb[4][6];
            #pragma unroll
            for (int dy=0; dy<4; dy++){
                float4 x4 = *(const float4*)&xs[b][i][dy][tg*4];
                float2 x2 = *(const float2*)&xs[b][i][dy][tg*4+4];
                xb[dy][0]=pack1(x4.x); xb[dy][1]=pack1(x4.y); xb[dy][2]=pack1(x4.z);
                xb[dy][3]=pack1(x4.w); xb[dy][4]=pack1(x2.x); xb[dy][5]=pack1(x2.y);
            }
            #pragma unroll
            for (int dy=0;dy<3;dy++)
                #pragma unroll
                for (int dx=0;dx<3;dx++){
                    ulonglong2 w2 = *(const ulonglong2*)&ws[b][i][dy*3+dx][og*4];
                    #pragma unroll
                    for (int yr=0;yr<2;yr++)
                        #pragma unroll
                        for (int t=0;t<4;t++){
                            acc2[yr][0][t] = fma2r(xb[dy+yr][t+dx], w2.x, acc2[yr][0][t]);
                            acc2[yr][1][t] = fma2r(xb[dy+yr][t+dx], w2.y, acc2[yr][1][t]);
                        }
                }
        }
        if (s<15){
            const int nb = b^1;
            #pragma unroll
            for (int r=0;r<5;r++){
                int idx = tid + r*288;
                if (idx < 1216){
                    int ci = idx/152, rem = idx - ci*152, dy = rem/38, cx = rem - dy*38;
                    xs[nb][ci][dy][cx] = xr[r];
                }
            }
            #pragma unroll
            for (int r=0;r<8;r++) ((float4*)ws[nb])[tid + r*288] = wr[r];
        }
        __syncthreads();
    }

    #pragma unroll
    for (int yr=0;yr<2;yr++){
        int y = y0 + yr;
        #pragma unroll
        for (int p=0;p<2;p++){
            int oc0 = og*4 + 2*p;
            float b0 = bias[oc0], b1 = bias[oc0+1];
            #pragma unroll
            for (int t=0;t<4;t++){
                int xc = tg*4+t;
                float v0, v1; unpack2(acc2[yr][p][t], v0, v1);
                g_za[((size_t)n*256 + oc0)*HWTOK + y*WW + xc]   = v0 + b0;
                g_za[((size_t)n*256 + oc0+1)*HWTOK + y*WW + xc] = v1 + b1;
            }
        }
    }
}

// ---------------- attention: K,V smem-resident, 11 warps, 2 q/thread (R4 config) ----------------
#define ATTN_THREADS 352
#define ATTN_ACT 324
#define ATTN_SMEM (2*HWTOK*HEADC*4)

__global__ void attn_kernel()
{
    extern __shared__ float sm[];
    float* Ks = sm;                       // [1296][16]
    float* Vs = sm + HWTOK*HEADC;
    const int nh = blockIdx.y; const int n = nh >> 3; const int h = nh & 7;
    const int tid = threadIdx.x;
    const float* kp = g_k + ((size_t)n*RCH + h*HEADC)*HWTOK;
    const float* vp = g_v + ((size_t)n*RCH + h*HEADC)*HWTOK;
    #pragma unroll
    for (int c=0;c<HEADC;c++){
        for (int j=tid;j<HWTOK;j+=ATTN_THREADS){
            Ks[j*HEADC+c] = kp[(size_t)c*HWTOK+j];
            Vs[j*HEADC+c] = vp[(size_t)c*HWTOK+j];
        }
    }
    __syncthreads();
    if (tid >= ATTN_ACT) return;

    const int q0 = blockIdx.x*648 + tid;     // q0, q0+324
    const float* qp = g_q + ((size_t)n*RCH + h*HEADC)*HWTOK;
    ull q2[2][8], a2[2][8]; float l[2];
    #pragma unroll
    for (int u=0;u<2;u++){
        int q = q0 + u*ATTN_ACT;
        #pragma unroll
        for (int p=0;p<8;p++){
            q2[u][p] = pack2(qp[(size_t)(2*p)*HWTOK+q]*LOG2E,
                             qp[(size_t)(2*p+1)*HWTOK+q]*LOG2E);
            a2[u][p] = 0ull;
        }
        l[u] = 0.f;
    }
    #pragma unroll 2
    for (int j=0;j<HWTOK;j++){
        const ulonglong2* kr = (const ulonglong2*)(Ks + j*HEADC);
        ulonglong2 k0 = kr[0], k1 = kr[1], k2 = kr[2], k3 = kr[3];
        float e[2];
        #pragma unroll
        for (int u=0;u<2;u++){
            ull s = mul2(q2[u][0], k0.x);
            s = fma2r(q2[u][1], k0.y, s);
            s = fma2r(q2[u][2], k1.x, s);
            s = fma2r(q2[u][3], k1.y, s);
            s = fma2r(q2[u][4], k2.x, s);
            s = fma2r(q2[u][5], k2.y, s);
            s = fma2r(q2[u][6], k3.x, s);
            s = fma2r(q2[u][7], k3.y, s);
            float s0, s1; unpack2(s, s0, s1);
            e[u] = ex2_fast(s0 + s1);
            l[u] += e[u];
        }
        const ulonglong2* vr = (const ulonglong2*)(Vs + j*HEADC);
        ulonglong2 v0 = vr[0], v1 = vr[1], v2 = vr[2], v3 = vr[3];
        ull vv[8] = {v0.x,v0.y,v1.x,v1.y,v2.x,v2.y,v3.x,v3.y};
        #pragma unroll
        for (int u=0;u<2;u++){
            ull eb = pack1(e[u]);
            #pragma unroll
            for (int p=0;p<8;p++) a2[u][p] = fma2r(eb, vv[p], a2[u][p]);
        }
    }
    float* ap = g_za + ((size_t)n*256 + 128 + h*HEADC)*HWTOK;
    #pragma unroll
    for (int u=0;u<2;u++){
        int q = q0 + u*ATTN_ACT;
        float inv = 1.f / l[u];
        #pragma unroll
        for (int p=0;p<8;p++){
            float lo, hi; unpack2(a2[u][p], lo, hi);
            ap[(size_t)(2*p)*HWTOK + q]   = lo*inv;
            ap[(size_t)(2*p+1)*HWTOK + q] = hi*inv;
        }
    }
}

// ---------------- launch ----------------
extern "C" void kernel_launch(void* const* d_in, const int* in_sizes, int n_in,
                              void* d_out, int out_size)
{
    const float* x      = (const float*)d_in[0];
    const float* w_in   = (const float*)d_in[1];
    const float* b_in   = (const float*)d_in[2];
    const float* w_conv = (const float*)d_in[3];
    const float* b_conv = (const float*)d_in[4];
    const float* wq     = (const float*)d_in[5];
    const float* wk     = (const float*)d_in[6];
    const float* wv     = (const float*)d_in[7];
    const float* w_i    = (const float*)d_in[8];
    const float* b_i    = (const float*)d_in[9];
    // d_in[10], d_in[11]: w_f/b_f unused (first timestep: f*c0 == 0)
    const float* w_g    = (const float*)d_in[12];
    const float* b_g    = (const float*)d_in[13];
    const float* w_o    = (const float*)d_in[14];
    const float* b_o    = (const float*)d_in[15];
    const float* w_out  = (const float*)d_in[16];
    const float* b_out  = (const float*)d_in[17];
    float* out = (float*)d_out;

    cudaFuncSetAttribute(attn_kernel, cudaFuncAttributeMaxDynamicSharedMemorySize, ATTN_SMEM);

    repack_all<<<1280,256>>>(w_in, wq, wk, wv, w_i, w_g, w_o, w_out, w_conv);

    inproj_kernel<<<dim3(21,NIMG),256>>>(x, b_in);                   // -> g_xtp
    conv3x3_kernel<<<dim3(18,NIMG),288>>>(b_conv);                   // -> g_za[:, :128]
    qkv_kernel<<<dim3(21,NIMG,3),256>>>();                           // -> g_q/g_k/g_v
    attn_kernel<<<dim3(2, NIMG*NHEAD), ATTN_THREADS, ATTN_SMEM>>>(); // -> g_za[:,128:]
    gates_gemm_kernel<<<dim3(21,NIMG,3),256>>>();                    // -> g_pre
    lstm_act_kernel<<<(ACT_N4+255)/256,256>>>(b_i, b_g, b_o);        // -> g_h
    outproj_kernel<<<dim3(21,NIMG),256>>>(b_out, out);               // -> d_out
}